// round 1
// baseline (speedup 1.0000x reference)
#include <cuda_runtime.h>
#include <cstdint>

#define NC 30
#define WIDTH 64
#define D 32
#define KP (D / 2)        // 16 float2 (f32x2) chunks per row
#define TPB 256
#define EPT 2             // batch elements per thread

// Hypernetwork outputs (scratch; device globals — no allocation allowed)
__device__ __align__(16) float g_W[WIDTH * D];
__device__ __align__(16) float g_U[WIDTH * D];
__device__ float g_B[WIDTH];
__device__ float g_wu[WIDTH];

// ---------------- packed f32x2 helpers (FFMA2 is PTX-only) ----------------
__device__ __forceinline__ unsigned long long pack2(float x, float y) {
    unsigned long long r;
    asm("mov.b64 %0, {%1, %2};" : "=l"(r) : "f"(x), "f"(y));
    return r;
}
__device__ __forceinline__ void unpack2(unsigned long long v, float& x, float& y) {
    asm("mov.b64 {%0, %1}, %2;" : "=f"(x), "=f"(y) : "l"(v));
}
__device__ __forceinline__ unsigned long long ffma2(unsigned long long a,
                                                    unsigned long long b,
                                                    unsigned long long c) {
    unsigned long long d;
    asm("fma.rn.f32x2 %0, %1, %2, %3;" : "=l"(d) : "l"(a), "l"(b), "l"(c));
    return d;
}
__device__ __forceinline__ float tanh_fast(float x) {
    float y;
    asm("tanh.approx.f32 %0, %1;" : "=f"(y) : "f"(x));
    return y;
}

// ---------------- hypernetwork prologue: RBF + Linear -> Wt, Ut, Bt, wu ----
__global__ void hyper_kernel(
    const float* __restrict__ t,
    const float* __restrict__ Wc, const float* __restrict__ Wls,
    const float* __restrict__ Wlw, const float* __restrict__ Wlb,
    const float* __restrict__ Uc, const float* __restrict__ Uls,
    const float* __restrict__ Ulw, const float* __restrict__ Ulb,
    const float* __restrict__ Bc, const float* __restrict__ Bls,
    const float* __restrict__ Blw, const float* __restrict__ Blb)
{
    __shared__ float phiW[NC], phiU[NC], phiB[NC];
    __shared__ float sW[WIDTH * D], sU[WIDTH * D];
    const int tid = threadIdx.x;
    const float tv = t[0];

    if (tid < NC) {
        float d0 = fabsf(tv - Wc[tid]) / expf(Wls[tid]);
        phiW[tid] = expf(-d0 * d0);
        float d1 = fabsf(tv - Uc[tid]) / expf(Uls[tid]);
        phiU[tid] = expf(-d1 * d1);
        float d2 = fabsf(tv - Bc[tid]) / expf(Bls[tid]);
        phiB[tid] = expf(-d2 * d2);
    }
    __syncthreads();

    for (int i = tid; i < WIDTH * D; i += blockDim.x) {
        float aw = Wlb[i], au = Ulb[i];
#pragma unroll
        for (int j = 0; j < NC; j++) {
            aw = fmaf(phiW[j], Wlw[i * NC + j], aw);
            au = fmaf(phiU[j], Ulw[i * NC + j], au);
        }
        sW[i] = aw;  sU[i] = au;
        g_W[i] = aw; g_U[i] = au;
    }
    if (tid < WIDTH) {
        float ab = Blb[tid];
#pragma unroll
        for (int j = 0; j < NC; j++) ab = fmaf(phiB[j], Blw[tid * NC + j], ab);
        g_B[tid] = ab;
    }
    __syncthreads();

    if (tid < WIDTH) {
        float s = 0.f;
#pragma unroll
        for (int k = 0; k < D; k++) s = fmaf(sW[tid * D + k], sU[tid * D + k], s);
        g_wu[tid] = s;
    }
}

// ---------------- main fused kernel -----------------------------------------
// h = tanh(z @ Wt^T + Bt); dz = (h @ Ut)/64; dlogp = -((1-h^2) @ wu)/64
__global__ void __launch_bounds__(TPB) cnf_main_kernel(
    const float* __restrict__ z, float* __restrict__ out, int batch)
{
    __shared__ unsigned long long sW[WIDTH * KP];   // [w][kpair]
    __shared__ unsigned long long sU[WIDTH * KP];
    __shared__ float sB[WIDTH];
    __shared__ float swu[WIDTH];

    const int tid = threadIdx.x;
    {
        const unsigned long long* gw = (const unsigned long long*)g_W;
        const unsigned long long* gu = (const unsigned long long*)g_U;
        for (int i = tid; i < WIDTH * KP; i += TPB) { sW[i] = gw[i]; sU[i] = gu[i]; }
        if (tid < WIDTH) { sB[tid] = g_B[tid]; swu[tid] = g_wu[tid]; }
    }
    __syncthreads();

    const long long base = ((long long)blockIdx.x * TPB + tid) * EPT;
    if (base >= batch) return;

    // Load z rows: contiguous 128B per element, fully coalesced at line level.
    unsigned long long zs[EPT][KP];
#pragma unroll
    for (int e = 0; e < EPT; e++) {
        const ulonglong2* zp = (const ulonglong2*)(z + (base + e) * D);
#pragma unroll
        for (int q = 0; q < KP / 2; q++) {
            ulonglong2 v = zp[q];
            zs[e][2 * q]     = v.x;
            zs[e][2 * q + 1] = v.y;
        }
    }

    unsigned long long dz[EPT][KP];
#pragma unroll
    for (int e = 0; e < EPT; e++)
#pragma unroll
        for (int k = 0; k < KP; k++) dz[e][k] = 0ull;   // bit pattern (0.f, 0.f)
    float tr[EPT];
#pragma unroll
    for (int e = 0; e < EPT; e++) tr[e] = 0.f;

#pragma unroll 4
    for (int w = 0; w < WIDTH; w++) {
        const unsigned long long* wrow = &sW[w * KP];
        const unsigned long long* urow = &sU[w * KP];

        // GEMM1: per-w dot, k packed in f32x2 (weight pair straight from LDS.64)
        unsigned long long acc[EPT];
#pragma unroll
        for (int e = 0; e < EPT; e++) acc[e] = 0ull;
#pragma unroll
        for (int k = 0; k < KP; k++) {
            const unsigned long long wk = wrow[k];
#pragma unroll
            for (int e = 0; e < EPT; e++) acc[e] = ffma2(zs[e][k], wk, acc[e]);
        }

        const float bw  = sB[w];
        const float wuv = swu[w];
        unsigned long long hh[EPT];
#pragma unroll
        for (int e = 0; e < EPT; e++) {
            float ax, ay;
            unpack2(acc[e], ax, ay);
            const float h = tanh_fast(ax + ay + bw);
            const float gth = fmaf(-h, h, 1.0f);           // 1 - h^2
            tr[e] = fmaf(gth, wuv, tr[e]);
            hh[e] = pack2(h, h);
        }

        // GEMM2: dz[k] += h * Ut[w][k], k packed in f32x2
#pragma unroll
        for (int k = 0; k < KP; k++) {
            const unsigned long long uk = urow[k];
#pragma unroll
            for (int e = 0; e < EPT; e++) dz[e][k] = ffma2(hh[e], uk, dz[e][k]);
        }
    }

    const float inv = 1.0f / (float)WIDTH;
#pragma unroll
    for (int e = 0; e < EPT; e++) {
        float4* op = (float4*)(out + (base + e) * D);
#pragma unroll
        for (int q = 0; q < KP / 2; q++) {
            float x0, y0, x1, y1;
            unpack2(dz[e][2 * q],     x0, y0);
            unpack2(dz[e][2 * q + 1], x1, y1);
            op[q] = make_float4(x0 * inv, y0 * inv, x1 * inv, y1 * inv);
        }
    }
    float* ol = out + (long long)batch * D;   // dlogp region follows dz region
#pragma unroll
    for (int e = 0; e < EPT; e++) ol[base + e] = -tr[e] * inv;
}

// ---------------- launch -----------------------------------------------------
extern "C" void kernel_launch(void* const* d_in, const int* in_sizes, int n_in,
                              void* d_out, int out_size) {
    const float* t   = (const float*)d_in[0];
    const float* z   = (const float*)d_in[1];
    // d_in[2] = logp_z (unused by the reference math)
    const float* Wc  = (const float*)d_in[3];
    const float* Wls = (const float*)d_in[4];
    const float* Wlw = (const float*)d_in[5];
    const float* Wlb = (const float*)d_in[6];
    const float* Uc  = (const float*)d_in[7];
    const float* Uls = (const float*)d_in[8];
    const float* Ulw = (const float*)d_in[9];
    const float* Ulb = (const float*)d_in[10];
    const float* Bc  = (const float*)d_in[11];
    const float* Bls = (const float*)d_in[12];
    const float* Blw = (const float*)d_in[13];
    const float* Blb = (const float*)d_in[14];

    const int batch = in_sizes[1] / D;

    hyper_kernel<<<1, 256>>>(t, Wc, Wls, Wlw, Wlb,
                             Uc, Uls, Ulw, Ulb,
                             Bc, Bls, Blw, Blb);

    const int grid = (batch + TPB * EPT - 1) / (TPB * EPT);
    cnf_main_kernel<<<grid, TPB>>>(z, (float*)d_out, batch);
}

// round 9
// speedup vs baseline: 1.0615x; 1.0615x over previous
#include <cuda_runtime.h>
#include <cuda_fp16.h>
#include <cstdint>

#define NC 30
#define WIDTH 64
#define D 32
#define TPB 128
#define CTAS 444   // 148 SMs * 3

// ---------------- device-global packed weight fragments ---------------------
// All fragment tables are [lane 0..31][word] so each lane's words are contiguous.
__device__ uint32_t g_fWh[32 * 32];  // GEMM1 B hi: word = nt*4 + kb*2 + r   (k-permuted)
__device__ uint32_t g_fWl[32 * 32];  // GEMM1 B lo residual
__device__ uint32_t g_fUh[32 * 32];  // GEMM2 B hi: word = nt2*8 + kb*2 + r  (canonical, unscaled)
__device__ uint32_t g_fUl[32 * 32];  // GEMM2 B lo residual
__device__ float    g_fb [4 * 16];   // [j][nt*2+c] bias (fp32)
__device__ float    g_fwu[4 * 16];   // [j][nt*2+c] wu * (1/64)

// ---------------- helpers ----------------------------------------------------
__device__ __forceinline__ float tanh_fast(float x) {
    float y; asm("tanh.approx.f32 %0, %1;" : "=f"(y) : "f"(x)); return y;
}
__device__ __forceinline__ uint32_t f2h2(float lo, float hi) {
    __half2 h = __floats2half2_rn(lo, hi);            // .x = lo (low half)
    return *reinterpret_cast<uint32_t*>(&h);
}
__device__ __forceinline__ float2 h22f2(uint32_t v) {
    __half2 h = *reinterpret_cast<__half2*>(&v);
    return __half22float2(h);                          // .x = low half
}

#define MMA16816(c, a0, a1, a2, a3, b0, b1)                                  \
    asm volatile("mma.sync.aligned.m16n8k16.row.col.f32.f16.f16.f32 "        \
        "{%0,%1,%2,%3}, {%4,%5,%6,%7}, {%8,%9}, {%0,%1,%2,%3};"              \
        : "+f"((c)[0]), "+f"((c)[1]), "+f"((c)[2]), "+f"((c)[3])             \
        : "r"(a0), "r"(a1), "r"(a2), "r"(a3), "r"(b0), "r"(b1))

// ---------------- hypernetwork prologue + fragment packing -------------------
__global__ void hyper_kernel(
    const float* __restrict__ t,
    const float* __restrict__ Wc, const float* __restrict__ Wls,
    const float* __restrict__ Wlw, const float* __restrict__ Wlb,
    const float* __restrict__ Uc, const float* __restrict__ Uls,
    const float* __restrict__ Ulw, const float* __restrict__ Ulb,
    const float* __restrict__ Bc, const float* __restrict__ Bls,
    const float* __restrict__ Blw, const float* __restrict__ Blb)
{
    __shared__ float phiW[NC], phiU[NC], phiB[NC];
    __shared__ float sW[WIDTH * D], sU[WIDTH * D], sB[WIDTH], swu[WIDTH];
    const int tid = threadIdx.x;
    const float tv = t[0];
    const float inv = 1.0f / (float)WIDTH;

    if (tid < NC) {
        float d0 = fabsf(tv - Wc[tid]) / expf(Wls[tid]); phiW[tid] = expf(-d0 * d0);
        float d1 = fabsf(tv - Uc[tid]) / expf(Uls[tid]); phiU[tid] = expf(-d1 * d1);
        float d2 = fabsf(tv - Bc[tid]) / expf(Bls[tid]); phiB[tid] = expf(-d2 * d2);
    }
    __syncthreads();

    for (int i = tid; i < WIDTH * D; i += blockDim.x) {
        float aw = Wlb[i], au = Ulb[i];
#pragma unroll
        for (int jj = 0; jj < NC; jj++) {
            aw = fmaf(phiW[jj], Wlw[i * NC + jj], aw);
            au = fmaf(phiU[jj], Ulw[i * NC + jj], au);
        }
        sW[i] = aw; sU[i] = au;
    }
    if (tid < WIDTH) {
        float ab = Blb[tid];
#pragma unroll
        for (int jj = 0; jj < NC; jj++) ab = fmaf(phiB[jj], Blw[tid * NC + jj], ab);
        sB[tid] = ab;
    }
    __syncthreads();

    if (tid < WIDTH) {
        float s = 0.f;
#pragma unroll
        for (int k = 0; k < D; k++) s = fmaf(sW[tid * D + k], sU[tid * D + k], s);
        swu[tid] = s;
    }
    __syncthreads();

    // GEMM1 B frags (k-permuted to match direct z loads):
    // lane l = g*4+j ; word iw = nt*4 + kb*2 + r
    // value = half2(Wt[n][c], Wt[n][c+1]), n = nt*8+g, c = 16*kb + 4*j + 2*r
    for (int idx = tid; idx < 1024; idx += blockDim.x) {
        int l = idx >> 5, iw = idx & 31;
        int gg = l >> 2, jj = l & 3;
        int nt = iw >> 2, kb = (iw >> 1) & 1, r = iw & 1;
        int n = nt * 8 + gg, c = 16 * kb + 4 * jj + 2 * r;
        float v0 = sW[n * D + c], v1 = sW[n * D + c + 1];
        __half h0 = __float2half_rn(v0), h1 = __float2half_rn(v1);
        __half e0 = __float2half_rn(v0 - __half2float(h0));
        __half e1 = __float2half_rn(v1 - __half2float(h1));
        __half2 ph = __halves2half2(h0, h1), pl = __halves2half2(e0, e1);
        g_fWh[l * 32 + iw] = *reinterpret_cast<uint32_t*>(&ph);
        g_fWl[l * 32 + iw] = *reinterpret_cast<uint32_t*>(&pl);
    }
    // GEMM2 B frags (canonical layout, U unscaled):
    // word iw = nt2*8 + kb*2 + r ; value = half2(U[k0][n], U[k0+1][n]),
    // n = nt2*8+g, k0 = 16*kb + 8*r + 2*j
    for (int idx = tid; idx < 1024; idx += blockDim.x) {
        int l = idx >> 5, iw = idx & 31;
        int gg = l >> 2, jj = l & 3;
        int nt2 = iw >> 3, kb = (iw >> 1) & 3, r = iw & 1;
        int n = nt2 * 8 + gg, k0 = 16 * kb + 8 * r + 2 * jj;
        float u0 = sU[k0 * D + n], u1 = sU[(k0 + 1) * D + n];
        __half h0 = __float2half_rn(u0), h1 = __float2half_rn(u1);
        __half e0 = __float2half_rn(u0 - __half2float(h0));
        __half e1 = __float2half_rn(u1 - __half2float(h1));
        __half2 ph = __halves2half2(h0, h1), pl = __halves2half2(e0, e1);
        g_fUh[l * 32 + iw] = *reinterpret_cast<uint32_t*>(&ph);
        g_fUl[l * 32 + iw] = *reinterpret_cast<uint32_t*>(&pl);
    }
    // bias / wu tables: [j][nt*2+c] -> w = nt*8 + 2*j + c
    if (tid < 64) {
        int jj = tid >> 4, iw = tid & 15;
        int nt = iw >> 1, c = iw & 1;
        int w = nt * 8 + 2 * jj + c;
        g_fb[tid]  = sB[w];
        g_fwu[tid] = swu[w] * inv;
    }
}

// ---------------- main mma.sync kernel ---------------------------------------
__global__ void __launch_bounds__(TPB, 3) cnf_main_kernel(
    const float* __restrict__ z, float* __restrict__ out,
    int batch, int ntiles, int nwarps)
{
    const int lane = threadIdx.x & 31;
    const int g = lane >> 2, j = lane & 3;
    const int wslot = blockIdx.x * (TPB / 32) + (threadIdx.x >> 5);
    const float inv = 1.0f / (float)WIDTH;

    // hoist GEMM1 hi weights (32 regs)
    uint32_t Wh[32];
    {
        const uint4* p = (const uint4*)(g_fWh + lane * 32);
#pragma unroll
        for (int q = 0; q < 8; q++) {
            uint4 a = p[q];
            Wh[4 * q] = a.x; Wh[4 * q + 1] = a.y; Wh[4 * q + 2] = a.z; Wh[4 * q + 3] = a.w;
        }
    }
    const uint4*  pWl = (const uint4*)(g_fWl + lane * 32);
    const uint4*  pUh = (const uint4*)(g_fUh + lane * 32);
    const uint4*  pUl = (const uint4*)(g_fUl + lane * 32);
    const float4* pb  = (const float4*)(g_fb  + j * 16);
    const float4* pwu = (const float4*)(g_fwu + j * 16);

    for (int tile = wslot; tile < ntiles; tile += nwarps) {
        const long long row0 = (long long)tile * 16;
        const long long rgA = row0 + g, rgB = row0 + g + 8;
        const long long rA = rgA < batch ? rgA : (long long)batch - 1;
        const long long rB = rgB < batch ? rgB : (long long)batch - 1;

        // ---- A loads: 4 coalesced LDG.128 (rows g, g+8 ; kblocks 0,1)
        float4 A0[2], A1[2];
#pragma unroll
        for (int kb = 0; kb < 2; kb++) {
            A0[kb] = *(const float4*)(z + rA * D + kb * 16 + j * 4);
            A1[kb] = *(const float4*)(z + rB * D + kb * 16 + j * 4);
        }
        // ---- fp16 hi/lo split of A (permuted-k frag order: a0=4j,4j+1 a2=4j+2,4j+3)
        uint32_t zh[2][4], zl[2][4];
#pragma unroll
        for (int kb = 0; kb < 2; kb++) {
            zh[kb][0] = f2h2(A0[kb].x, A0[kb].y);
            zh[kb][1] = f2h2(A1[kb].x, A1[kb].y);
            zh[kb][2] = f2h2(A0[kb].z, A0[kb].w);
            zh[kb][3] = f2h2(A1[kb].z, A1[kb].w);
            float2 e0 = h22f2(zh[kb][0]), e1 = h22f2(zh[kb][1]);
            float2 e2 = h22f2(zh[kb][2]), e3 = h22f2(zh[kb][3]);
            zl[kb][0] = f2h2(A0[kb].x - e0.x, A0[kb].y - e0.y);
            zl[kb][1] = f2h2(A1[kb].x - e1.x, A1[kb].y - e1.y);
            zl[kb][2] = f2h2(A0[kb].z - e2.x, A0[kb].w - e2.y);
            zl[kb][3] = f2h2(A1[kb].z - e3.x, A1[kb].w - e3.y);
        }

        // ---- C1 init = bias (folded into accumulator)
        float C[8][4];
        float bias[16];
        {
            float4 b0 = pb[0], b1 = pb[1], b2 = pb[2], b3 = pb[3];
            bias[0]=b0.x; bias[1]=b0.y; bias[2]=b0.z; bias[3]=b0.w;
            bias[4]=b1.x; bias[5]=b1.y; bias[6]=b1.z; bias[7]=b1.w;
            bias[8]=b2.x; bias[9]=b2.y; bias[10]=b2.z; bias[11]=b2.w;
            bias[12]=b3.x; bias[13]=b3.y; bias[14]=b3.z; bias[15]=b3.w;
        }
#pragma unroll
        for (int nt = 0; nt < 8; nt++) {
            C[nt][0] = bias[nt * 2];     C[nt][1] = bias[nt * 2 + 1];
            C[nt][2] = bias[nt * 2];     C[nt][3] = bias[nt * 2 + 1];
        }

        // ---- GEMM1: x3 fp16 (hi*hi, lo*hi, hi*lo)
#pragma unroll
        for (int nt = 0; nt < 8; nt++) {
            uint4 wl = pWl[nt];   // words: kb0r0, kb0r1, kb1r0, kb1r1
            MMA16816(C[nt], zh[0][0], zh[0][1], zh[0][2], zh[0][3], Wh[nt*4+0], Wh[nt*4+1]);
            MMA16816(C[nt], zh[1][0], zh[1][1], zh[1][2], zh[1][3], Wh[nt*4+2], Wh[nt*4+3]);
            MMA16816(C[nt], zl[0][0], zl[0][1], zl[0][2], zl[0][3], Wh[nt*4+0], Wh[nt*4+1]);
            MMA16816(C[nt], zl[1][0], zl[1][1], zl[1][2], zl[1][3], Wh[nt*4+2], Wh[nt*4+3]);
            MMA16816(C[nt], zh[0][0], zh[0][1], zh[0][2], zh[0][3], wl.x, wl.y);
            MMA16816(C[nt], zh[1][0], zh[1][1], zh[1][2], zh[1][3], wl.z, wl.w);
        }

        // ---- epilogue 1: tanh, exact trace, re-pack h as GEMM2 A-frags
        float wu[16];
        {
            float4 w0 = pwu[0], w1 = pwu[1], w2 = pwu[2], w3 = pwu[3];
            wu[0]=w0.x; wu[1]=w0.y; wu[2]=w0.z; wu[3]=w0.w;
            wu[4]=w1.x; wu[5]=w1.y; wu[6]=w1.z; wu[7]=w1.w;
            wu[8]=w2.x; wu[9]=w2.y; wu[10]=w2.z; wu[11]=w2.w;
            wu[12]=w3.x; wu[13]=w3.y; wu[14]=w3.z; wu[15]=w3.w;
        }
        float tr0 = 0.f, tr1 = 0.f;
        uint32_t Ah[4][4], Al[4][4];
#pragma unroll
        for (int nt = 0; nt < 8; nt++) {
            float h0 = tanh_fast(C[nt][0]);
            float h1 = tanh_fast(C[nt][1]);
            float h2 = tanh_fast(C[nt][2]);
            float h3 = tanh_fast(C[nt][3]);
            tr0 = fmaf(fmaf(-h0, h0, 1.f), wu[nt * 2],     tr0);
            tr0 = fmaf(fmaf(-h1, h1, 1.f), wu[nt * 2 + 1], tr0);
            tr1 = fmaf(fmaf(-h2, h2, 1.f), wu[nt * 2],     tr1);
            tr1 = fmaf(fmaf(-h3, h3, 1.f), wu[nt * 2 + 1], tr1);
            int kb = nt >> 1, base = (nt & 1) * 2;
            uint32_t p01 = f2h2(h0, h1), p23 = f2h2(h2, h3);
            Ah[kb][base]     = p01;      // a0/a2 slots: rows g
            Ah[kb][base + 1] = p23;      // a1/a3 slots: rows g+8
            float2 e01 = h22f2(p01), e23 = h22f2(p23);
            Al[kb][base]     = f2h2(h0 - e01.x, h1 - e01.y);
            Al[kb][base + 1] = f2h2(h2 - e23.x, h3 - e23.y);
        }

        // ---- GEMM2: x3 fp16 (U unscaled; /64 applied at store in fp32)
        float C2[4][4];
#pragma unroll
        for (int nt2 = 0; nt2 < 4; nt2++) {
            C2[nt2][0] = 0.f; C2[nt2][1] = 0.f; C2[nt2][2] = 0.f; C2[nt2][3] = 0.f;
            uint4 q0 = pUh[nt2 * 2], q1 = pUh[nt2 * 2 + 1];
            uint4 u0 = pUl[nt2 * 2], u1 = pUl[nt2 * 2 + 1];
            const uint32_t uh[8] = {q0.x, q0.y, q0.z, q0.w, q1.x, q1.y, q1.z, q1.w};
            const uint32_t ul[8] = {u0.x, u0.y, u0.z, u0.w, u1.x, u1.y, u1.z, u1.w};
#pragma unroll
            for (int kb = 0; kb < 4; kb++) {
                MMA16816(C2[nt2], Ah[kb][0], Ah[kb][1], Ah[kb][2], Ah[kb][3],
                         uh[kb * 2], uh[kb * 2 + 1]);
                MMA16816(C2[nt2], Al[kb][0], Al[kb][1], Al[kb][2], Al[kb][3],
                         uh[kb * 2], uh[kb * 2 + 1]);
                MMA16816(C2[nt2], Ah[kb][0], Ah[kb][1], Ah[kb][2], Ah[kb][3],
                         ul[kb * 2], ul[kb * 2 + 1]);
            }
        }

        // ---- trace reduction across j (lane bits 0,1)
        tr0 += __shfl_xor_sync(0xffffffffu, tr0, 1);
        tr0 += __shfl_xor_sync(0xffffffffu, tr0, 2);
        tr1 += __shfl_xor_sync(0xffffffffu, tr1, 1);
        tr1 += __shfl_xor_sync(0xffffffffu, tr1, 2);

        // ---- stores: dz (float2 per nt2 per row) and dlogp
        if (rgA < batch) {
            float* orow = out + rgA * D + 2 * j;
#pragma unroll
            for (int nt2 = 0; nt2 < 4; nt2++)
                *(float2*)(orow + nt2 * 8) = make_float2(C2[nt2][0] * inv, C2[nt2][1] * inv);
            if (j == 0) out[(long long)batch * D + rgA] = -tr0;
        }
        if (rgB < batch) {
            float* orow = out + rgB * D + 2 * j;
#pragma unroll
            for (int nt2 = 0; nt2 < 4; nt2++)
                *(float2*)(orow + nt2 * 8) = make_float2(C2[nt2][2] * inv, C2[nt2][3] * inv);
            if (j == 0) out[(long long)batch * D + rgB] = -tr1;
        }
    }
}

// ---------------- launch -----------------------------------------------------
extern "C" void kernel_launch(void* const* d_in, const int* in_sizes, int n_in,
                              void* d_out, int out_size) {
    const float* t   = (const float*)d_in[0];
    const float* z   = (const float*)d_in[1];
    const float* Wc  = (const float*)d_in[3];
    const float* Wls = (const float*)d_in[4];
    const float* Wlw = (const float*)d_in[5];
    const float* Wlb = (const float*)d_in[6];
    const float* Uc  = (const float*)d_in[7];
    const float* Uls = (const float*)d_in[8];
    const float* Ulw = (const float*)d_in[9];
    const float* Ulb = (const float*)d_in[10];
    const float* Bc  = (const float*)d_in[11];
    const float* Bls = (const float*)d_in[12];
    const float* Blw = (const float*)d_in[13];
    const float* Blb = (const float*)d_in[14];

    const int batch = in_sizes[1] / D;
    const int ntiles = (batch + 15) / 16;
    const int nwarps = CTAS * (TPB / 32);

    hyper_kernel<<<1, 256>>>(t, Wc, Wls, Wlw, Wlb,
                             Uc, Uls, Ulw, Ulb,
                             Bc, Bls, Blw, Blb);

    cnf_main_kernel<<<CTAS, TPB>>>(z, (float*)d_out, batch, ntiles, nwarps);
}

// round 12
// speedup vs baseline: 2.3405x; 2.2048x over previous
#include <cuda_runtime.h>
#include <cuda_fp16.h>
#include <cstdint>

#define NC 30
#define WIDTH 64
#define D 32
#define TPB 128
#define CTAS 444   // 148 SMs * 3

// ---------------- device-global packed weight fragments ---------------------
// Layout: [q][lane][4 words] (q = uint4 chunk index), so a CTA copy is linear
// and a per-lane uint4 read is ((uint4*)g)[q*32 + lane].
__device__ uint32_t g_fWh[8 * 32 * 4];  // GEMM1 B hi: q=nt,      word=kb*2+r (k-permuted)
__device__ uint32_t g_fWl[8 * 32 * 4];  // GEMM1 B lo residual
__device__ uint32_t g_fUh[8 * 32 * 4];  // GEMM2 B hi: q=nt2*2+h, word pairs (canonical, unscaled)
__device__ uint32_t g_fUl[8 * 32 * 4];  // GEMM2 B lo residual
__device__ float    g_fb [4 * 16];      // [j][nt*2+c] bias (fp32)
__device__ float    g_fwu[4 * 16];      // [j][nt*2+c] wu * (1/64)

// ---------------- helpers ----------------------------------------------------
__device__ __forceinline__ float tanh_fast(float x) {
    float y; asm("tanh.approx.f32 %0, %1;" : "=f"(y) : "f"(x)); return y;
}
__device__ __forceinline__ uint32_t f2h2(float lo, float hi) {
    __half2 h = __floats2half2_rn(lo, hi);            // .x = lo (low half)
    return *reinterpret_cast<uint32_t*>(&h);
}
__device__ __forceinline__ float2 h22f2(uint32_t v) {
    __half2 h = *reinterpret_cast<__half2*>(&v);
    return __half22float2(h);                          // .x = low half
}

#define MMA16816(c, a0, a1, a2, a3, b0, b1)                                  \
    asm volatile("mma.sync.aligned.m16n8k16.row.col.f32.f16.f16.f32 "        \
        "{%0,%1,%2,%3}, {%4,%5,%6,%7}, {%8,%9}, {%0,%1,%2,%3};"              \
        : "+f"((c)[0]), "+f"((c)[1]), "+f"((c)[2]), "+f"((c)[3])             \
        : "r"(a0), "r"(a1), "r"(a2), "r"(a3), "r"(b0), "r"(b1))

// ---------------- hypernetwork prologue + fragment packing -------------------
__global__ void hyper_kernel(
    const float* __restrict__ t,
    const float* __restrict__ Wc, const float* __restrict__ Wls,
    const float* __restrict__ Wlw, const float* __restrict__ Wlb,
    const float* __restrict__ Uc, const float* __restrict__ Uls,
    const float* __restrict__ Ulw, const float* __restrict__ Ulb,
    const float* __restrict__ Bc, const float* __restrict__ Bls,
    const float* __restrict__ Blw, const float* __restrict__ Blb)
{
    __shared__ float phiW[NC], phiU[NC], phiB[NC];
    __shared__ float sW[WIDTH * D], sU[WIDTH * D], sB[WIDTH], swu[WIDTH];
    const int tid = threadIdx.x;
    const float tv = t[0];
    const float inv = 1.0f / (float)WIDTH;

    if (tid < NC) {
        float d0 = fabsf(tv - Wc[tid]) / expf(Wls[tid]); phiW[tid] = expf(-d0 * d0);
        float d1 = fabsf(tv - Uc[tid]) / expf(Uls[tid]); phiU[tid] = expf(-d1 * d1);
        float d2 = fabsf(tv - Bc[tid]) / expf(Bls[tid]); phiB[tid] = expf(-d2 * d2);
    }
    __syncthreads();

    for (int i = tid; i < WIDTH * D; i += blockDim.x) {
        float aw = Wlb[i], au = Ulb[i];
#pragma unroll
        for (int jj = 0; jj < NC; jj++) {
            aw = fmaf(phiW[jj], Wlw[i * NC + jj], aw);
            au = fmaf(phiU[jj], Ulw[i * NC + jj], au);
        }
        sW[i] = aw; sU[i] = au;
    }
    if (tid < WIDTH) {
        float ab = Blb[tid];
#pragma unroll
        for (int jj = 0; jj < NC; jj++) ab = fmaf(phiB[jj], Blw[tid * NC + jj], ab);
        sB[tid] = ab;
    }
    __syncthreads();

    if (tid < WIDTH) {
        float s = 0.f;
#pragma unroll
        for (int k = 0; k < D; k++) s = fmaf(sW[tid * D + k], sU[tid * D + k], s);
        swu[tid] = s;
    }
    __syncthreads();

    // GEMM1 B frags (k-permuted to match direct z loads):
    // lane l = g*4+j ; iw = nt*4 + kb*2 + r ; dst = nt*128 + l*4 + (kb*2+r)
    // value = half2(Wt[n][c], Wt[n][c+1]), n = nt*8+g, c = 16*kb + 4*j + 2*r
    for (int idx = tid; idx < 1024; idx += blockDim.x) {
        int l = idx >> 5, iw = idx & 31;
        int gg = l >> 2, jj = l & 3;
        int nt = iw >> 2, kb = (iw >> 1) & 1, r = iw & 1;
        int n = nt * 8 + gg, c = 16 * kb + 4 * jj + 2 * r;
        float v0 = sW[n * D + c], v1 = sW[n * D + c + 1];
        __half h0 = __float2half_rn(v0), h1 = __float2half_rn(v1);
        __half e0 = __float2half_rn(v0 - __half2float(h0));
        __half e1 = __float2half_rn(v1 - __half2float(h1));
        __half2 ph = __halves2half2(h0, h1), pl = __halves2half2(e0, e1);
        int dst = nt * 128 + l * 4 + (iw & 3);
        g_fWh[dst] = *reinterpret_cast<uint32_t*>(&ph);
        g_fWl[dst] = *reinterpret_cast<uint32_t*>(&pl);
    }
    // GEMM2 B frags (canonical layout, U unscaled):
    // iw = nt2*8 + kb*2 + r ; q = iw>>2 ; dst = q*128 + l*4 + (iw&3)
    // value = half2(U[k0][n], U[k0+1][n]), n = nt2*8+g, k0 = 16*kb + 8*r + 2*j
    for (int idx = tid; idx < 1024; idx += blockDim.x) {
        int l = idx >> 5, iw = idx & 31;
        int gg = l >> 2, jj = l & 3;
        int nt2 = iw >> 3, kb = (iw >> 1) & 3, r = iw & 1;
        int n = nt2 * 8 + gg, k0 = 16 * kb + 8 * r + 2 * jj;
        float u0 = sU[k0 * D + n], u1 = sU[(k0 + 1) * D + n];
        __half h0 = __float2half_rn(u0), h1 = __float2half_rn(u1);
        __half e0 = __float2half_rn(u0 - __half2float(h0));
        __half e1 = __float2half_rn(u1 - __half2float(h1));
        __half2 ph = __halves2half2(h0, h1), pl = __halves2half2(e0, e1);
        int dst = (iw >> 2) * 128 + l * 4 + (iw & 3);
        g_fUh[dst] = *reinterpret_cast<uint32_t*>(&ph);
        g_fUl[dst] = *reinterpret_cast<uint32_t*>(&pl);
    }
    // bias / wu tables: [j][nt*2+c] -> w = nt*8 + 2*j + c
    if (tid < 64) {
        int jj = tid >> 4, iw = tid & 15;
        int nt = iw >> 1, c = iw & 1;
        int w = nt * 8 + 2 * jj + c;
        g_fb[tid]  = sB[w];
        g_fwu[tid] = swu[w] * inv;
    }
}

// ---------------- main mma.sync kernel ---------------------------------------
__global__ void __launch_bounds__(TPB, 3) cnf_main_kernel(
    const float* __restrict__ z, float* __restrict__ out,
    int batch, int ntiles, int nwarps)
{
    __shared__ uint4 sWl[256], sUh[256], sUl[256];   // [q][lane], 4KB each
    __shared__ float sb[64], swu[64];

    const int tid  = threadIdx.x;
    const int lane = tid & 31;
    const int g = lane >> 2, j = lane & 3;
    const int wslot = blockIdx.x * (TPB / 32) + (tid >> 5);
    const float inv = 1.0f / (float)WIDTH;

    // CTA prologue: linear, coalesced copies of the fragment tables into smem.
    {
        const uint4* gWl = (const uint4*)g_fWl;
        const uint4* gUh = (const uint4*)g_fUh;
        const uint4* gUl = (const uint4*)g_fUl;
#pragma unroll
        for (int i = tid; i < 256; i += TPB) {
            sWl[i] = gWl[i]; sUh[i] = gUh[i]; sUl[i] = gUl[i];
        }
        if (tid < 64) { sb[tid] = g_fb[tid]; swu[tid] = g_fwu[tid]; }
    }

    // hoist GEMM1 hi weights (32 regs): uint4 chunk q=nt at [nt*32 + lane]
    uint32_t Wh[32];
    {
        const uint4* gWh = (const uint4*)g_fWh;
#pragma unroll
        for (int nt = 0; nt < 8; nt++) {
            uint4 a = gWh[nt * 32 + lane];
            Wh[nt * 4] = a.x; Wh[nt * 4 + 1] = a.y; Wh[nt * 4 + 2] = a.z; Wh[nt * 4 + 3] = a.w;
        }
    }
    __syncthreads();

    for (int tile = wslot; tile < ntiles; tile += nwarps) {
        const long long row0 = (long long)tile * 16;
        const long long rgA = row0 + g, rgB = row0 + g + 8;
        const long long rA = rgA < batch ? rgA : (long long)batch - 1;
        const long long rB = rgB < batch ? rgB : (long long)batch - 1;

        // ---- A loads: 4 coalesced LDG.128 (rows g, g+8 ; kblocks 0,1)
        float4 A0[2], A1[2];
#pragma unroll
        for (int kb = 0; kb < 2; kb++) {
            A0[kb] = *(const float4*)(z + rA * D + kb * 16 + j * 4);
            A1[kb] = *(const float4*)(z + rB * D + kb * 16 + j * 4);
        }
        // ---- fp16 hi/lo split of A (permuted-k frag order)
        uint32_t zh[2][4], zl[2][4];
#pragma unroll
        for (int kb = 0; kb < 2; kb++) {
            zh[kb][0] = f2h2(A0[kb].x, A0[kb].y);
            zh[kb][1] = f2h2(A1[kb].x, A1[kb].y);
            zh[kb][2] = f2h2(A0[kb].z, A0[kb].w);
            zh[kb][3] = f2h2(A1[kb].z, A1[kb].w);
            float2 e0 = h22f2(zh[kb][0]), e1 = h22f2(zh[kb][1]);
            float2 e2 = h22f2(zh[kb][2]), e3 = h22f2(zh[kb][3]);
            zl[kb][0] = f2h2(A0[kb].x - e0.x, A0[kb].y - e0.y);
            zl[kb][1] = f2h2(A1[kb].x - e1.x, A1[kb].y - e1.y);
            zl[kb][2] = f2h2(A0[kb].z - e2.x, A0[kb].w - e2.y);
            zl[kb][3] = f2h2(A1[kb].z - e3.x, A1[kb].w - e3.y);
        }

        // ---- C1 init = bias (folded into accumulator; broadcast LDS)
        float C[8][4];
        float bias[16];
        {
            const float4* pb = (const float4*)(sb + j * 16);
            float4 b0 = pb[0], b1 = pb[1], b2 = pb[2], b3 = pb[3];
            bias[0]=b0.x; bias[1]=b0.y; bias[2]=b0.z; bias[3]=b0.w;
            bias[4]=b1.x; bias[5]=b1.y; bias[6]=b1.z; bias[7]=b1.w;
            bias[8]=b2.x; bias[9]=b2.y; bias[10]=b2.z; bias[11]=b2.w;
            bias[12]=b3.x; bias[13]=b3.y; bias[14]=b3.z; bias[15]=b3.w;
        }
#pragma unroll
        for (int nt = 0; nt < 8; nt++) {
            C[nt][0] = bias[nt * 2];     C[nt][1] = bias[nt * 2 + 1];
            C[nt][2] = bias[nt * 2];     C[nt][3] = bias[nt * 2 + 1];
        }

        // ---- GEMM1: x3 fp16 (hi*hi, lo*hi, hi*lo); Wl from conflict-free LDS.128
#pragma unroll
        for (int nt = 0; nt < 8; nt++) {
            uint4 wl = sWl[nt * 32 + lane];   // words: kb0r0, kb0r1, kb1r0, kb1r1
            MMA16816(C[nt], zh[0][0], zh[0][1], zh[0][2], zh[0][3], Wh[nt*4+0], Wh[nt*4+1]);
            MMA16816(C[nt], zh[1][0], zh[1][1], zh[1][2], zh[1][3], Wh[nt*4+2], Wh[nt*4+3]);
            MMA16816(C[nt], zl[0][0], zl[0][1], zl[0][2], zl[0][3], Wh[nt*4+0], Wh[nt*4+1]);
            MMA16816(C[nt], zl[1][0], zl[1][1], zl[1][2], zl[1][3], Wh[nt*4+2], Wh[nt*4+3]);
            MMA16816(C[nt], zh[0][0], zh[0][1], zh[0][2], zh[0][3], wl.x, wl.y);
            MMA16816(C[nt], zh[1][0], zh[1][1], zh[1][2], zh[1][3], wl.z, wl.w);
        }

        // ---- epilogue 1: tanh, exact trace, re-pack h as GEMM2 A-frags
        float wu[16];
        {
            const float4* pwu = (const float4*)(swu + j * 16);
            float4 w0 = pwu[0], w1 = pwu[1], w2 = pwu[2], w3 = pwu[3];
            wu[0]=w0.x; wu[1]=w0.y; wu[2]=w0.z; wu[3]=w0.w;
            wu[4]=w1.x; wu[5]=w1.y; wu[6]=w1.z; wu[7]=w1.w;
            wu[8]=w2.x; wu[9]=w2.y; wu[10]=w2.z; wu[11]=w2.w;
            wu[12]=w3.x; wu[13]=w3.y; wu[14]=w3.z; wu[15]=w3.w;
        }
        float tr0 = 0.f, tr1 = 0.f;
        uint32_t Ah[4][4], Al[4][4];
#pragma unroll
        for (int nt = 0; nt < 8; nt++) {
            float h0 = tanh_fast(C[nt][0]);
            float h1 = tanh_fast(C[nt][1]);
            float h2 = tanh_fast(C[nt][2]);
            float h3 = tanh_fast(C[nt][3]);
            tr0 = fmaf(fmaf(-h0, h0, 1.f), wu[nt * 2],     tr0);
            tr0 = fmaf(fmaf(-h1, h1, 1.f), wu[nt * 2 + 1], tr0);
            tr1 = fmaf(fmaf(-h2, h2, 1.f), wu[nt * 2],     tr1);
            tr1 = fmaf(fmaf(-h3, h3, 1.f), wu[nt * 2 + 1], tr1);
            int kb = nt >> 1, base = (nt & 1) * 2;
            uint32_t p01 = f2h2(h0, h1), p23 = f2h2(h2, h3);
            Ah[kb][base]     = p01;      // a0/a2 slots: rows g
            Ah[kb][base + 1] = p23;      // a1/a3 slots: rows g+8
            float2 e01 = h22f2(p01), e23 = h22f2(p23);
            Al[kb][base]     = f2h2(h0 - e01.x, h1 - e01.y);
            Al[kb][base + 1] = f2h2(h2 - e23.x, h3 - e23.y);
        }

        // ---- GEMM2: x3 fp16 (U unscaled; /64 applied at store in fp32)
        float C2[4][4];
#pragma unroll
        for (int nt2 = 0; nt2 < 4; nt2++) {
            C2[nt2][0] = 0.f; C2[nt2][1] = 0.f; C2[nt2][2] = 0.f; C2[nt2][3] = 0.f;
            uint4 q0 = sUh[(nt2 * 2)     * 32 + lane];
            uint4 q1 = sUh[(nt2 * 2 + 1) * 32 + lane];
            uint4 u0 = sUl[(nt2 * 2)     * 32 + lane];
            uint4 u1 = sUl[(nt2 * 2 + 1) * 32 + lane];
            const uint32_t uh[8] = {q0.x, q0.y, q0.z, q0.w, q1.x, q1.y, q1.z, q1.w};
            const uint32_t ul[8] = {u0.x, u0.y, u0.z, u0.w, u1.x, u1.y, u1.z, u1.w};
#pragma unroll
            for (int kb = 0; kb < 4; kb++) {
                MMA16816(C2[nt2], Ah[kb][0], Ah[kb][1], Ah[kb][2], Ah[kb][3],
                         uh[kb * 2], uh[kb * 2 + 1]);
                MMA16816(C2[nt2], Al[kb][0], Al[kb][1], Al[kb][2], Al[kb][3],
                         uh[kb * 2], uh[kb * 2 + 1]);
                MMA16816(C2[nt2], Ah[kb][0], Ah[kb][1], Ah[kb][2], Ah[kb][3],
                         ul[kb * 2], ul[kb * 2 + 1]);
            }
        }

        // ---- trace reduction across j (lane bits 0,1)
        tr0 += __shfl_xor_sync(0xffffffffu, tr0, 1);
        tr0 += __shfl_xor_sync(0xffffffffu, tr0, 2);
        tr1 += __shfl_xor_sync(0xffffffffu, tr1, 1);
        tr1 += __shfl_xor_sync(0xffffffffu, tr1, 2);

        // ---- stores: dz (float2 per nt2 per row) and dlogp
        if (rgA < batch) {
            float* orow = out + rgA * D + 2 * j;
#pragma unroll
            for (int nt2 = 0; nt2 < 4; nt2++)
                *(float2*)(orow + nt2 * 8) = make_float2(C2[nt2][0] * inv, C2[nt2][1] * inv);
            if (j == 0) out[(long long)batch * D + rgA] = -tr0;
        }
        if (rgB < batch) {
            float* orow = out + rgB * D + 2 * j;
#pragma unroll
            for (int nt2 = 0; nt2 < 4; nt2++)
                *(float2*)(orow + nt2 * 8) = make_float2(C2[nt2][2] * inv, C2[nt2][3] * inv);
            if (j == 0) out[(long long)batch * D + rgB] = -tr1;
        }
    }
}

// ---------------- launch -----------------------------------------------------
extern "C" void kernel_launch(void* const* d_in, const int* in_sizes, int n_in,
                              void* d_out, int out_size) {
    const float* t   = (const float*)d_in[0];
    const float* z   = (const float*)d_in[1];
    const float* Wc  = (const float*)d_in[3];
    const float* Wls = (const float*)d_in[4];
    const float* Wlw = (const float*)d_in[5];
    const float* Wlb = (const float*)d_in[6];
    const float* Uc  = (const float*)d_in[7];
    const float* Uls = (const float*)d_in[8];
    const float* Ulw = (const float*)d_in[9];
    const float* Ulb = (const float*)d_in[10];
    const float* Bc  = (const float*)d_in[11];
    const float* Bls = (const float*)d_in[12];
    const float* Blw = (const float*)d_in[13];
    const float* Blb = (const float*)d_in[14];

    const int batch = in_sizes[1] / D;
    const int ntiles = (batch + 15) / 16;
    const int nwarps = CTAS * (TPB / 32);

    hyper_kernel<<<1, 256>>>(t, Wc, Wls, Wlw, Wlb,
                             Uc, Uls, Ulw, Ulb,
                             Bc, Bls, Blw, Blb);

    cnf_main_kernel<<<CTAS, TPB>>>(z, (float*)d_out, batch, ntiles, nwarps);
}

// round 13
// speedup vs baseline: 3.3102x; 1.4143x over previous
#include <cuda_runtime.h>
#include <cuda_fp16.h>
#include <cstdint>

#define NC 30
#define WIDTH 64
#define D 32
#define TPB 128
#define CTAS 444      // 148 SMs * 3
#define HC_CTAS 16    // hyper_compute grid

// ---------------- device-global scratch --------------------------------------
__device__ float    g_W[WIDTH * D];     // fp32 Wt
__device__ float    g_U[WIDTH * D];     // fp32 Ut
__device__ float    g_B[WIDTH];
// Fragment tables: [q][lane][4 words] so CTA copies are linear and per-lane
// uint4 reads are ((uint4*)g)[q*32 + lane].
__device__ uint32_t g_fWh[8 * 32 * 4];  // GEMM1 B hi (k-permuted)
__device__ uint32_t g_fWl[8 * 32 * 4];  // GEMM1 B lo residual
__device__ uint32_t g_fUh[8 * 32 * 4];  // GEMM2 B hi (canonical, unscaled)
__device__ uint32_t g_fUl[8 * 32 * 4];  // GEMM2 B lo residual
__device__ float    g_fb [4 * 16];      // [j][nt*2+c] bias (fp32)
__device__ float    g_fwu[4 * 16];      // [j][nt*2+c] wu * (1/64)

// ---------------- helpers ----------------------------------------------------
__device__ __forceinline__ float tanh_fast(float x) {
    float y; asm("tanh.approx.f32 %0, %1;" : "=f"(y) : "f"(x)); return y;
}
__device__ __forceinline__ uint32_t f2h2(float lo, float hi) {
    __half2 h = __floats2half2_rn(lo, hi);            // .x = lo (low half)
    return *reinterpret_cast<uint32_t*>(&h);
}
__device__ __forceinline__ float2 h22f2(uint32_t v) {
    __half2 h = *reinterpret_cast<__half2*>(&v);
    return __half22float2(h);                          // .x = low half
}

#define MMA16816(c, a0, a1, a2, a3, b0, b1)                                  \
    asm volatile("mma.sync.aligned.m16n8k16.row.col.f32.f16.f16.f32 "        \
        "{%0,%1,%2,%3}, {%4,%5,%6,%7}, {%8,%9}, {%0,%1,%2,%3};"              \
        : "+f"((c)[0]), "+f"((c)[1]), "+f"((c)[2]), "+f"((c)[3])             \
        : "r"(a0), "r"(a1), "r"(a2), "r"(a3), "r"(b0), "r"(b1))

// ---------------- hyper stage 1: parallel RBF-linear -------------------------
__global__ void hyper_compute(
    const float* __restrict__ t,
    const float* __restrict__ Wc, const float* __restrict__ Wls,
    const float* __restrict__ Wlw, const float* __restrict__ Wlb,
    const float* __restrict__ Uc, const float* __restrict__ Uls,
    const float* __restrict__ Ulw, const float* __restrict__ Ulb,
    const float* __restrict__ Bc, const float* __restrict__ Bls,
    const float* __restrict__ Blw, const float* __restrict__ Blb)
{
    __shared__ float phiW[NC], phiU[NC], phiB[NC];
    const int tid = threadIdx.x;
    const int gid = blockIdx.x * blockDim.x + tid;
    const float tv = t[0];

    if (tid < NC) {
        float d0 = fabsf(tv - Wc[tid]) / expf(Wls[tid]); phiW[tid] = expf(-d0 * d0);
        float d1 = fabsf(tv - Uc[tid]) / expf(Uls[tid]); phiU[tid] = expf(-d1 * d1);
        float d2 = fabsf(tv - Bc[tid]) / expf(Bls[tid]); phiB[tid] = expf(-d2 * d2);
    }
    __syncthreads();

    if (gid < WIDTH * D) {
        float aw = Wlb[gid], au = Ulb[gid];
        const float* wr = Wlw + gid * NC;
        const float* ur = Ulw + gid * NC;
#pragma unroll
        for (int jj = 0; jj < NC; jj++) {
            aw = fmaf(phiW[jj], wr[jj], aw);
            au = fmaf(phiU[jj], ur[jj], au);
        }
        g_W[gid] = aw; g_U[gid] = au;
    }
    if (gid < WIDTH) {
        float ab = Blb[gid];
        const float* br = Blw + gid * NC;
#pragma unroll
        for (int jj = 0; jj < NC; jj++) ab = fmaf(phiB[jj], br[jj], ab);
        g_B[gid] = ab;
    }
}

// ---------------- hyper stage 2: fragment packing (1 small CTA) --------------
__global__ void hyper_pack()
{
    __shared__ float sW[WIDTH * D], sU[WIDTH * D], sB[WIDTH], swu[WIDTH];
    const int tid = threadIdx.x;
    const float inv = 1.0f / (float)WIDTH;

    for (int i = tid; i < WIDTH * D; i += blockDim.x) { sW[i] = g_W[i]; sU[i] = g_U[i]; }
    if (tid < WIDTH) sB[tid] = g_B[tid];
    __syncthreads();

    if (tid < WIDTH) {
        float s = 0.f;
#pragma unroll
        for (int k = 0; k < D; k++) s = fmaf(sW[tid * D + k], sU[tid * D + k], s);
        swu[tid] = s;
    }
    __syncthreads();

    // GEMM1 B frags (k-permuted to match direct z loads):
    // lane l = g*4+j ; iw = nt*4 + kb*2 + r ; dst = nt*128 + l*4 + (kb*2+r)
    // value = half2(Wt[n][c], Wt[n][c+1]), n = nt*8+g, c = 16*kb + 4*j + 2*r
    for (int idx = tid; idx < 1024; idx += blockDim.x) {
        int l = idx >> 5, iw = idx & 31;
        int gg = l >> 2, jj = l & 3;
        int nt = iw >> 2, kb = (iw >> 1) & 1, r = iw & 1;
        int n = nt * 8 + gg, c = 16 * kb + 4 * jj + 2 * r;
        float v0 = sW[n * D + c], v1 = sW[n * D + c + 1];
        __half h0 = __float2half_rn(v0), h1 = __float2half_rn(v1);
        __half e0 = __float2half_rn(v0 - __half2float(h0));
        __half e1 = __float2half_rn(v1 - __half2float(h1));
        __half2 ph = __halves2half2(h0, h1), pl = __halves2half2(e0, e1);
        int dst = nt * 128 + l * 4 + (iw & 3);
        g_fWh[dst] = *reinterpret_cast<uint32_t*>(&ph);
        g_fWl[dst] = *reinterpret_cast<uint32_t*>(&pl);
    }
    // GEMM2 B frags (canonical layout, U unscaled):
    // iw = nt2*8 + kb*2 + r ; dst = (iw>>2)*128 + l*4 + (iw&3)
    // value = half2(U[k0][n], U[k0+1][n]), n = nt2*8+g, k0 = 16*kb + 8*r + 2*j
    for (int idx = tid; idx < 1024; idx += blockDim.x) {
        int l = idx >> 5, iw = idx & 31;
        int gg = l >> 2, jj = l & 3;
        int nt2 = iw >> 3, kb = (iw >> 1) & 3, r = iw & 1;
        int n = nt2 * 8 + gg, k0 = 16 * kb + 8 * r + 2 * jj;
        float u0 = sU[k0 * D + n], u1 = sU[(k0 + 1) * D + n];
        __half h0 = __float2half_rn(u0), h1 = __float2half_rn(u1);
        __half e0 = __float2half_rn(u0 - __half2float(h0));
        __half e1 = __float2half_rn(u1 - __half2float(h1));
        __half2 ph = __halves2half2(h0, h1), pl = __halves2half2(e0, e1);
        int dst = (iw >> 2) * 128 + l * 4 + (iw & 3);
        g_fUh[dst] = *reinterpret_cast<uint32_t*>(&ph);
        g_fUl[dst] = *reinterpret_cast<uint32_t*>(&pl);
    }
    // bias / wu tables: [j][nt*2+c] -> w = nt*8 + 2*j + c
    if (tid < 64) {
        int jj = tid >> 4, iw = tid & 15;
        int nt = iw >> 1, c = iw & 1;
        int w = nt * 8 + 2 * jj + c;
        g_fb[tid]  = sB[w];
        g_fwu[tid] = swu[w] * inv;
    }
}

// ---------------- main mma.sync kernel ---------------------------------------
__global__ void __launch_bounds__(TPB, 3) cnf_main_kernel(
    const float* __restrict__ z, float* __restrict__ out,
    int batch, int ntiles, int nwarps)
{
    __shared__ uint4 sWl[256], sUh[256], sUl[256];   // [q][lane], 4KB each
    __shared__ float sb[64], swu[64];

    const int tid  = threadIdx.x;
    const int lane = tid & 31;
    const int g = lane >> 2, j = lane & 3;
    const int wslot = blockIdx.x * (TPB / 32) + (tid >> 5);
    const float inv = 1.0f / (float)WIDTH;

    // CTA prologue: linear, coalesced copies of the fragment tables into smem.
    {
        const uint4* gWl = (const uint4*)g_fWl;
        const uint4* gUh = (const uint4*)g_fUh;
        const uint4* gUl = (const uint4*)g_fUl;
#pragma unroll
        for (int i = tid; i < 256; i += TPB) {
            sWl[i] = gWl[i]; sUh[i] = gUh[i]; sUl[i] = gUl[i];
        }
        if (tid < 64) { sb[tid] = g_fb[tid]; swu[tid] = g_fwu[tid]; }
    }

    // hoist GEMM1 hi weights (32 regs)
    uint32_t Wh[32];
    {
        const uint4* gWh = (const uint4*)g_fWh;
#pragma unroll
        for (int nt = 0; nt < 8; nt++) {
            uint4 a = gWh[nt * 32 + lane];
            Wh[nt * 4] = a.x; Wh[nt * 4 + 1] = a.y; Wh[nt * 4 + 2] = a.z; Wh[nt * 4 + 3] = a.w;
        }
    }
    __syncthreads();

    // ---- software-pipelined tile loop: A regs recycled, next-tile LDGs issued
    //      right after the fp16 conversion consumes the current values.
    float4 A0[2], A1[2];
    long long tile = wslot;
    if (tile < ntiles) {
        const long long row0 = tile * 16;
        const long long rA = min(row0 + g,     (long long)batch - 1);
        const long long rB = min(row0 + g + 8, (long long)batch - 1);
#pragma unroll
        for (int kb = 0; kb < 2; kb++) {
            A0[kb] = *(const float4*)(z + rA * D + kb * 16 + j * 4);
            A1[kb] = *(const float4*)(z + rB * D + kb * 16 + j * 4);
        }
    }

    for (; tile < ntiles; tile += nwarps) {
        const long long row0 = tile * 16;
        const long long rgA = row0 + g, rgB = row0 + g + 8;

        // ---- fp16 hi/lo split of A (permuted-k frag order)
        uint32_t zh[2][4], zl[2][4];
#pragma unroll
        for (int kb = 0; kb < 2; kb++) {
            zh[kb][0] = f2h2(A0[kb].x, A0[kb].y);
            zh[kb][1] = f2h2(A1[kb].x, A1[kb].y);
            zh[kb][2] = f2h2(A0[kb].z, A0[kb].w);
            zh[kb][3] = f2h2(A1[kb].z, A1[kb].w);
            float2 e0 = h22f2(zh[kb][0]), e1 = h22f2(zh[kb][1]);
            float2 e2 = h22f2(zh[kb][2]), e3 = h22f2(zh[kb][3]);
            zl[kb][0] = f2h2(A0[kb].x - e0.x, A0[kb].y - e0.y);
            zl[kb][1] = f2h2(A1[kb].x - e1.x, A1[kb].y - e1.y);
            zl[kb][2] = f2h2(A0[kb].z - e2.x, A0[kb].w - e2.y);
            zl[kb][3] = f2h2(A1[kb].z - e3.x, A1[kb].w - e3.y);
        }

        // ---- prefetch next tile's A (rides under the MMAs below)
        {
            const long long nxt = tile + nwarps;
            if (nxt < ntiles) {
                const long long nrow0 = nxt * 16;
                const long long rA = min(nrow0 + g,     (long long)batch - 1);
                const long long rB = min(nrow0 + g + 8, (long long)batch - 1);
#pragma unroll
                for (int kb = 0; kb < 2; kb++) {
                    A0[kb] = *(const float4*)(z + rA * D + kb * 16 + j * 4);
                    A1[kb] = *(const float4*)(z + rB * D + kb * 16 + j * 4);
                }
            }
        }

        // ---- C1 init = bias (folded into accumulator; broadcast LDS)
        float C[8][4];
        float bias[16];
        {
            const float4* pb = (const float4*)(sb + j * 16);
            float4 b0 = pb[0], b1 = pb[1], b2 = pb[2], b3 = pb[3];
            bias[0]=b0.x; bias[1]=b0.y; bias[2]=b0.z; bias[3]=b0.w;
            bias[4]=b1.x; bias[5]=b1.y; bias[6]=b1.z; bias[7]=b1.w;
            bias[8]=b2.x; bias[9]=b2.y; bias[10]=b2.z; bias[11]=b2.w;
            bias[12]=b3.x; bias[13]=b3.y; bias[14]=b3.z; bias[15]=b3.w;
        }
#pragma unroll
        for (int nt = 0; nt < 8; nt++) {
            C[nt][0] = bias[nt * 2];     C[nt][1] = bias[nt * 2 + 1];
            C[nt][2] = bias[nt * 2];     C[nt][3] = bias[nt * 2 + 1];
        }

        // ---- GEMM1: x3 fp16 (hi*hi, lo*hi, hi*lo); Wl from conflict-free LDS.128
#pragma unroll
        for (int nt = 0; nt < 8; nt++) {
            uint4 wl = sWl[nt * 32 + lane];   // words: kb0r0, kb0r1, kb1r0, kb1r1
            MMA16816(C[nt], zh[0][0], zh[0][1], zh[0][2], zh[0][3], Wh[nt*4+0], Wh[nt*4+1]);
            MMA16816(C[nt], zh[1][0], zh[1][1], zh[1][2], zh[1][3], Wh[nt*4+2], Wh[nt*4+3]);
            MMA16816(C[nt], zl[0][0], zl[0][1], zl[0][2], zl[0][3], Wh[nt*4+0], Wh[nt*4+1]);
            MMA16816(C[nt], zl[1][0], zl[1][1], zl[1][2], zl[1][3], Wh[nt*4+2], Wh[nt*4+3]);
            MMA16816(C[nt], zh[0][0], zh[0][1], zh[0][2], zh[0][3], wl.x, wl.y);
            MMA16816(C[nt], zh[1][0], zh[1][1], zh[1][2], zh[1][3], wl.z, wl.w);
        }

        // ---- epilogue 1: tanh, exact trace, re-pack h as GEMM2 A-frags
        float wu[16];
        {
            const float4* pwu = (const float4*)(swu + j * 16);
            float4 w0 = pwu[0], w1 = pwu[1], w2 = pwu[2], w3 = pwu[3];
            wu[0]=w0.x; wu[1]=w0.y; wu[2]=w0.z; wu[3]=w0.w;
            wu[4]=w1.x; wu[5]=w1.y; wu[6]=w1.z; wu[7]=w1.w;
            wu[8]=w2.x; wu[9]=w2.y; wu[10]=w2.z; wu[11]=w2.w;
            wu[12]=w3.x; wu[13]=w3.y; wu[14]=w3.z; wu[15]=w3.w;
        }
        float tr0 = 0.f, tr1 = 0.f;
        uint32_t Ah[4][4], Al[4][4];
#pragma unroll
        for (int nt = 0; nt < 8; nt++) {
            float h0 = tanh_fast(C[nt][0]);
            float h1 = tanh_fast(C[nt][1]);
            float h2 = tanh_fast(C[nt][2]);
            float h3 = tanh_fast(C[nt][3]);
            tr0 = fmaf(fmaf(-h0, h0, 1.f), wu[nt * 2],     tr0);
            tr0 = fmaf(fmaf(-h1, h1, 1.f), wu[nt * 2 + 1], tr0);
            tr1 = fmaf(fmaf(-h2, h2, 1.f), wu[nt * 2],     tr1);
            tr1 = fmaf(fmaf(-h3, h3, 1.f), wu[nt * 2 + 1], tr1);
            int kb = nt >> 1, base = (nt & 1) * 2;
            uint32_t p01 = f2h2(h0, h1), p23 = f2h2(h2, h3);
            Ah[kb][base]     = p01;      // a0/a2 slots: rows g
            Ah[kb][base + 1] = p23;      // a1/a3 slots: rows g+8
            float2 e01 = h22f2(p01), e23 = h22f2(p23);
            Al[kb][base]     = f2h2(h0 - e01.x, h1 - e01.y);
            Al[kb][base + 1] = f2h2(h2 - e23.x, h3 - e23.y);
        }

        // ---- GEMM2: x3 fp16 (U unscaled; /64 applied at store in fp32)
        float C2[4][4];
#pragma unroll
        for (int nt2 = 0; nt2 < 4; nt2++) {
            C2[nt2][0] = 0.f; C2[nt2][1] = 0.f; C2[nt2][2] = 0.f; C2[nt2][3] = 0.f;
            uint4 q0 = sUh[(nt2 * 2)     * 32 + lane];
            uint4 q1 = sUh[(nt2 * 2 + 1) * 32 + lane];
            uint4 u0 = sUl[(nt2 * 2)     * 32 + lane];
            uint4 u1 = sUl[(nt2 * 2 + 1) * 32 + lane];
            const uint32_t uh[8] = {q0.x, q0.y, q0.z, q0.w, q1.x, q1.y, q1.z, q1.w};
            const uint32_t ul[8] = {u0.x, u0.y, u0.z, u0.w, u1.x, u1.y, u1.z, u1.w};
#pragma unroll
            for (int kb = 0; kb < 4; kb++) {
                MMA16816(C2[nt2], Ah[kb][0], Ah[kb][1], Ah[kb][2], Ah[kb][3],
                         uh[kb * 2], uh[kb * 2 + 1]);
                MMA16816(C2[nt2], Al[kb][0], Al[kb][1], Al[kb][2], Al[kb][3],
                         uh[kb * 2], uh[kb * 2 + 1]);
                MMA16816(C2[nt2], Ah[kb][0], Ah[kb][1], Ah[kb][2], Ah[kb][3],
                         ul[kb * 2], ul[kb * 2 + 1]);
            }
        }

        // ---- trace reduction across j (lane bits 0,1)
        tr0 += __shfl_xor_sync(0xffffffffu, tr0, 1);
        tr0 += __shfl_xor_sync(0xffffffffu, tr0, 2);
        tr1 += __shfl_xor_sync(0xffffffffu, tr1, 1);
        tr1 += __shfl_xor_sync(0xffffffffu, tr1, 2);

        // ---- stores: dz (float2 per nt2 per row) and dlogp
        if (rgA < batch) {
            float* orow = out + rgA * D + 2 * j;
#pragma unroll
            for (int nt2 = 0; nt2 < 4; nt2++)
                *(float2*)(orow + nt2 * 8) = make_float2(C2[nt2][0] * inv, C2[nt2][1] * inv);
            if (j == 0) out[(long long)batch * D + rgA] = -tr0;
        }
        if (rgB < batch) {
            float* orow = out + rgB * D + 2 * j;
#pragma unroll
            for (int nt2 = 0; nt2 < 4; nt2++)
                *(float2*)(orow + nt2 * 8) = make_float2(C2[nt2][2] * inv, C2[nt2][3] * inv);
            if (j == 0) out[(long long)batch * D + rgB] = -tr1;
        }
    }
}

// ---------------- launch -----------------------------------------------------
extern "C" void kernel_launch(void* const* d_in, const int* in_sizes, int n_in,
                              void* d_out, int out_size) {
    const float* t   = (const float*)d_in[0];
    const float* z   = (const float*)d_in[1];
    const float* Wc  = (const float*)d_in[3];
    const float* Wls = (const float*)d_in[4];
    const float* Wlw = (const float*)d_in[5];
    const float* Wlb = (const float*)d_in[6];
    const float* Uc  = (const float*)d_in[7];
    const float* Uls = (const float*)d_in[8];
    const float* Ulw = (const float*)d_in[9];
    const float* Ulb = (const float*)d_in[10];
    const float* Bc  = (const float*)d_in[11];
    const float* Bls = (const float*)d_in[12];
    const float* Blw = (const float*)d_in[13];
    const float* Blb = (const float*)d_in[14];

    const int batch = in_sizes[1] / D;
    const int ntiles = (batch + 15) / 16;
    const int nwarps = CTAS * (TPB / 32);

    hyper_compute<<<HC_CTAS, 128>>>(t, Wc, Wls, Wlw, Wlb,
                                    Uc, Uls, Ulw, Ulb,
                                    Bc, Bls, Blw, Blb);
    hyper_pack<<<1, 256>>>();

    cnf_main_kernel<<<CTAS, TPB>>>(z, (float*)d_out, batch, ntiles, nwarps);
}